// round 1
// baseline (speedup 1.0000x reference)
#include <cuda_runtime.h>

// Problem constants
#define B_    16
#define CIN   512
#define N_    1024
#define HEADS_ 4
#define DH_   32
#define DV_   128
#define OTOT  768     // 128 (q) + 128 (k) + 512 (v) output channels

// ---------------- scratch (device globals; no allocation allowed) ----------
__device__ float g_Weff[OTOT * CIN];       // folded conv+BN weights
__device__ float g_beff[OTOT];             // folded bias
__device__ float g_q[B_ * 128 * N_];       // [b][h*32+d][n]
__device__ float g_k[B_ * 128 * N_];       // [b][h*32+d][n]
__device__ float g_v[B_ * 512 * N_];       // [b][h*128+c][n]
__device__ float g_pos[HEADS_ * DH_ * N_]; // [h][d][n]

// ---------------- kernel 1: fold BN into conv weights ----------------------
__global__ void fold_kernel(
    const float* __restrict__ Wq, const float* __restrict__ bq,
    const float* __restrict__ qg, const float* __restrict__ qb,
    const float* __restrict__ qm, const float* __restrict__ qv,
    const float* __restrict__ Wk, const float* __restrict__ bk,
    const float* __restrict__ kg, const float* __restrict__ kb,
    const float* __restrict__ km, const float* __restrict__ kv,
    const float* __restrict__ Wv, const float* __restrict__ bv,
    const float* __restrict__ vg, const float* __restrict__ vb,
    const float* __restrict__ vm, const float* __restrict__ vv)
{
    int idx = blockIdx.x * blockDim.x + threadIdx.x;
    if (idx >= OTOT * CIN) return;
    int o = idx >> 9;
    int c = idx & 511;
    const float *W, *bb, *g, *be, *mu, *va;
    int ol;
    if (o < 128)      { W = Wq; bb = bq; g = qg; be = qb; mu = qm; va = qv; ol = o; }
    else if (o < 256) { W = Wk; bb = bk; g = kg; be = kb; mu = km; va = kv; ol = o - 128; }
    else              { W = Wv; bb = bv; g = vg; be = vb; mu = vm; va = vv; ol = o - 256; }
    float s = g[ol] * rsqrtf(va[ol] + 1e-5f);
    g_Weff[idx] = W[ol * CIN + c] * s;
    if (c == 0) g_beff[o] = (bb[ol] - mu[ol]) * s + be[ol];
}

// ---------------- kernel 2: pos = rel_h + rel_w, [h][d][n] -----------------
__global__ void pos_kernel(const float* __restrict__ rel_h,
                           const float* __restrict__ rel_w)
{
    int idx = blockIdx.x * blockDim.x + threadIdx.x;  // HEADS*DH*N = 131072
    if (idx >= HEADS_ * DH_ * N_) return;
    int n  = idx & (N_ - 1);
    int hd = idx >> 10;            // h*32 + d
    int w  = n >> 5;
    int hh = n & 31;
    g_pos[idx] = rel_h[hd * 32 + hh] + rel_w[hd * 32 + w];
}

// ---------------- kernel 3: fused QKV GEMM  Y[768,1024] = Weff @ x_b -------
// Tile: BM=64, BN=64, BK=16; 256 threads; 4x4 microtile (cols tx + 16*j).
__global__ __launch_bounds__(256) void qkv_gemm(const float* __restrict__ x)
{
    __shared__ float As[16][68];   // As[kk][m]  (A transposed in smem)
    __shared__ float Bs[16][68];   // Bs[kk][n]

    int b  = blockIdx.z;
    int m0 = blockIdx.y * 64;
    int n0 = blockIdx.x * 64;
    int tid = threadIdx.x;
    int ty = tid >> 4, tx = tid & 15;
    const float* xb = x + (size_t)b * CIN * N_;

    float acc[4][4];
#pragma unroll
    for (int i = 0; i < 4; i++)
#pragma unroll
        for (int j = 0; j < 4; j++) acc[i][j] = 0.f;

    for (int k0 = 0; k0 < CIN; k0 += 16) {
        // load A tile 64x16 (one float4 per thread), transpose into smem
        {
            int row = tid >> 2;            // 0..63
            int cg  = (tid & 3) * 4;       // 0,4,8,12
            float4 av = *(const float4*)(g_Weff + (m0 + row) * CIN + k0 + cg);
            As[cg + 0][row] = av.x;
            As[cg + 1][row] = av.y;
            As[cg + 2][row] = av.z;
            As[cg + 3][row] = av.w;
        }
        // load B tile 16x64 (4 floats per thread, coalesced 64-float runs)
        {
            int nn = tid & 63;
            int kk = tid >> 6;             // 0..3
#pragma unroll
            for (int it = 0; it < 4; it++)
                Bs[kk + it * 4][nn] = xb[(size_t)(k0 + kk + it * 4) * N_ + n0 + nn];
        }
        __syncthreads();
#pragma unroll
        for (int kk = 0; kk < 16; kk++) {
            float4 a4 = *(const float4*)(&As[kk][4 * ty]);
            float a[4] = {a4.x, a4.y, a4.z, a4.w};
            float bv[4];
#pragma unroll
            for (int j = 0; j < 4; j++) bv[j] = Bs[kk][tx + 16 * j];
#pragma unroll
            for (int i = 0; i < 4; i++)
#pragma unroll
                for (int j = 0; j < 4; j++) acc[i][j] = fmaf(a[i], bv[j], acc[i][j]);
        }
        __syncthreads();
    }

    // epilogue: scatter into q / k / v layouts with bias
#pragma unroll
    for (int i = 0; i < 4; i++) {
        int o = m0 + 4 * ty + i;
        float bias = g_beff[o];
        float* dst;
        if (o < 128)      dst = g_q + (size_t)(b * 128 + o) * N_;
        else if (o < 256) dst = g_k + (size_t)(b * 128 + (o - 128)) * N_;
        else              dst = g_v + (size_t)(b * 512 + (o - 256)) * N_;
#pragma unroll
        for (int j = 0; j < 4; j++)
            dst[n0 + tx + 16 * j] = acc[i][j] + bias;
    }
}

// ---------------- kernel 4: fused flash attention + residual ---------------
// Per CTA: one (b, h) and 64 query rows.  d'=64 (q||pos vs k||q), dv=128.
// Smem (floats): Qs[64d][68], Ks[64d][68], Ps[64s][68], Vs[64s][132] (=Os[128][66])
#define ATTN_SMEM_FLOATS (3 * 64 * 68 + 64 * 132)
#define ATTN_SMEM_BYTES  (ATTN_SMEM_FLOATS * 4)

__global__ __launch_bounds__(256) void attn_kernel(const float* __restrict__ x,
                                                   float* __restrict__ out)
{
    extern __shared__ float sm[];
    float* Qs = sm;                 // Qs[d*68 + r]
    float* Ks = sm + 64 * 68;       // Ks[d*68 + s]
    float* Ps = sm + 2 * 64 * 68;   // Ps[s*68 + r]
    float* Vs = sm + 3 * 64 * 68;   // Vs[s*132 + c]   (reused as Os[c*66 + r])

    int n0 = blockIdx.x * 64;
    int h  = blockIdx.y;
    int b  = blockIdx.z;
    int tid = threadIdx.x;
    int ty = tid >> 4, tx = tid & 15;

    const float* qbh  = g_q + (size_t)(b * 128 + h * 32) * N_;   // [d][n]
    const float* kbh  = g_k + (size_t)(b * 128 + h * 32) * N_;
    const float* vbh  = g_v + (size_t)(b * 512 + h * 128) * N_;  // [c][n]
    const float* posh = g_pos + (size_t)h * 32 * N_;

    // fill Q' (q rows then pos rows), transposed: Qs[d][r]
    for (int idx = tid; idx < 64 * 64; idx += 256) {
        int r = idx & 63, d = idx >> 6;
        Qs[d * 68 + r] = (d < 32) ? qbh[(size_t)d * N_ + n0 + r]
                                  : posh[(size_t)(d - 32) * N_ + n0 + r];
    }

    float m[4], l[4], O[4][8];
#pragma unroll
    for (int i = 0; i < 4; i++) {
        m[i] = -1e30f; l[i] = 0.f;
#pragma unroll
        for (int jj = 0; jj < 8; jj++) O[i][jj] = 0.f;
    }
    __syncthreads();

    for (int s0 = 0; s0 < N_; s0 += 64) {
        // fill K' = [k ; q] (transposed) and V (transposed: Vs[s][c])
        for (int idx = tid; idx < 64 * 64; idx += 256) {
            int s = idx & 63, d = idx >> 6;
            Ks[d * 68 + s] = (d < 32) ? kbh[(size_t)d * N_ + s0 + s]
                                      : qbh[(size_t)(d - 32) * N_ + s0 + s];
        }
        for (int idx = tid; idx < 64 * 128; idx += 256) {
            int s = idx & 63, c = idx >> 6;
            Vs[s * 132 + c] = vbh[(size_t)c * N_ + s0 + s];
        }
        __syncthreads();

        // GEMM1: S[64r x 64s] over d'=64
        float S[4][4];
#pragma unroll
        for (int i = 0; i < 4; i++)
#pragma unroll
            for (int jj = 0; jj < 4; jj++) S[i][jj] = 0.f;

#pragma unroll 4
        for (int d = 0; d < 64; d++) {
            float4 a4 = *(const float4*)(Qs + d * 68 + 4 * ty);
            float a[4] = {a4.x, a4.y, a4.z, a4.w};
            float kk[4];
#pragma unroll
            for (int jj = 0; jj < 4; jj++) kk[jj] = Ks[d * 68 + tx + 16 * jj];
#pragma unroll
            for (int i = 0; i < 4; i++)
#pragma unroll
                for (int jj = 0; jj < 4; jj++) S[i][jj] = fmaf(a[i], kk[jj], S[i][jj]);
        }

        // online softmax (rows shared by 16 tx-lanes in each half-warp)
#pragma unroll
        for (int i = 0; i < 4; i++) {
            float rm = S[i][0];
#pragma unroll
            for (int jj = 1; jj < 4; jj++) rm = fmaxf(rm, S[i][jj]);
#pragma unroll
            for (int off = 8; off >= 1; off >>= 1)
                rm = fmaxf(rm, __shfl_xor_sync(0xffffffffu, rm, off));
            float mn = fmaxf(m[i], rm);
            float corr = __expf(m[i] - mn);
            m[i] = mn;
            float p[4], rs = 0.f;
#pragma unroll
            for (int jj = 0; jj < 4; jj++) { p[jj] = __expf(S[i][jj] - mn); rs += p[jj]; }
#pragma unroll
            for (int off = 8; off >= 1; off >>= 1)
                rs += __shfl_xor_sync(0xffffffffu, rs, off);
            l[i] = l[i] * corr + rs;
#pragma unroll
            for (int jj = 0; jj < 8; jj++) O[i][jj] *= corr;
#pragma unroll
            for (int jj = 0; jj < 4; jj++)
                Ps[(tx + 16 * jj) * 68 + 4 * ty + i] = p[jj];   // transposed: Ps[s][r]
        }
        __syncthreads();

        // GEMM2: O[64r x 128c] += P[64r x 64s] @ V[64s x 128c]
#pragma unroll 2
        for (int s = 0; s < 64; s++) {
            float4 p4 = *(const float4*)(Ps + s * 68 + 4 * ty);
            float p[4] = {p4.x, p4.y, p4.z, p4.w};
#pragma unroll
            for (int jj = 0; jj < 8; jj++) {
                float vv = Vs[s * 132 + tx + 16 * jj];
#pragma unroll
                for (int i = 0; i < 4; i++) O[i][jj] = fmaf(p[i], vv, O[i][jj]);
            }
        }
        __syncthreads();   // protects Ks/Vs/Ps reuse next iteration
    }

    // normalize + transpose through smem for coalesced global writes
#pragma unroll
    for (int i = 0; i < 4; i++) {
        float inv = 1.f / l[i];
#pragma unroll
        for (int jj = 0; jj < 8; jj++) O[i][jj] *= inv;
    }
    float* Os = Vs;   // reuse: Os[c*66 + r], 128*66 = 8448 floats = Vs size
#pragma unroll
    for (int i = 0; i < 4; i++)
#pragma unroll
        for (int jj = 0; jj < 8; jj++)
            Os[(tx + 16 * jj) * 66 + 4 * ty + i] = O[i][jj];
    __syncthreads();

    const float* xb = x   + (size_t)(b * 512 + h * 128) * N_;
    float*       ob = out + (size_t)(b * 512 + h * 128) * N_;
    for (int idx = tid; idx < 128 * 64; idx += 256) {
        int r = idx & 63, c = idx >> 6;
        ob[(size_t)c * N_ + n0 + r] = Os[c * 66 + r] + xb[(size_t)c * N_ + n0 + r];
    }
}

// ---------------- launcher -------------------------------------------------
extern "C" void kernel_launch(void* const* d_in, const int* in_sizes, int n_in,
                              void* d_out, int out_size)
{
    const float* x = (const float*)d_in[0];

    fold_kernel<<<(OTOT * CIN + 255) / 256, 256>>>(
        (const float*)d_in[1],  (const float*)d_in[2],
        (const float*)d_in[3],  (const float*)d_in[4],
        (const float*)d_in[5],  (const float*)d_in[6],
        (const float*)d_in[7],  (const float*)d_in[8],
        (const float*)d_in[9],  (const float*)d_in[10],
        (const float*)d_in[11], (const float*)d_in[12],
        (const float*)d_in[13], (const float*)d_in[14],
        (const float*)d_in[15], (const float*)d_in[16],
        (const float*)d_in[17], (const float*)d_in[18]);

    pos_kernel<<<(HEADS_ * DH_ * N_ + 255) / 256, 256>>>(
        (const float*)d_in[19], (const float*)d_in[20]);

    qkv_gemm<<<dim3(N_ / 64, OTOT / 64, B_), 256>>>(x);

    cudaFuncSetAttribute(attn_kernel,
                         cudaFuncAttributeMaxDynamicSharedMemorySize,
                         ATTN_SMEM_BYTES);
    attn_kernel<<<dim3(N_ / 64, HEADS_, B_), 256, ATTN_SMEM_BYTES>>>(x, (float*)d_out);
}

// round 5
// speedup vs baseline: 1.1584x; 1.1584x over previous
#include <cuda_runtime.h>

// Problem constants
#define B_    16
#define CIN   512
#define N_    1024
#define HEADS_ 4
#define DH_   32
#define DV_   128
#define OTOT  768     // 128 (q) + 128 (k) + 512 (v) output channels

typedef unsigned long long ull;

// ---------------- f32x2 packed helpers (sm_103a FFMA2 path) ----------------
__device__ __forceinline__ ull f2pk(float lo, float hi) {
    ull r; asm("mov.b64 %0, {%1, %2};" : "=l"(r) : "f"(lo), "f"(hi)); return r;
}
__device__ __forceinline__ ull f2dup(float x) {
    ull r; asm("mov.b64 %0, {%1, %1};" : "=l"(r) : "f"(x)); return r;
}
__device__ __forceinline__ void f2upk(ull v, float& lo, float& hi) {
    asm("mov.b64 {%0, %1}, %2;" : "=f"(lo), "=f"(hi) : "l"(v));
}
__device__ __forceinline__ ull f2fma(ull a, ull b, ull c) {
    ull d; asm("fma.rn.f32x2 %0, %1, %2, %3;" : "=l"(d) : "l"(a), "l"(b), "l"(c)); return d;
}
__device__ __forceinline__ ull f2mul(ull a, ull b) {
    ull d; asm("mul.rn.f32x2 %0, %1, %2;" : "=l"(d) : "l"(a), "l"(b)); return d;
}
__device__ __forceinline__ ull lds64(const float* p) {
    float2 v = *reinterpret_cast<const float2*>(p);
    return f2pk(v.x, v.y);
}

// ---------------- scratch (device globals; no allocation allowed) ----------
__device__ float g_Weff[OTOT * CIN];       // folded conv+BN weights
__device__ float g_beff[OTOT];             // folded bias
__device__ float g_q[B_ * 128 * N_];       // [b][h*32+d][n]
__device__ float g_k[B_ * 128 * N_];       // [b][h*32+d][n]
__device__ float g_v[B_ * 512 * N_];       // [b][h*128+c][n]
__device__ float g_pos[HEADS_ * DH_ * N_]; // [h][d][n]

// ---------------- kernel 1: fold BN into conv weights ----------------------
__global__ void fold_kernel(
    const float* __restrict__ Wq, const float* __restrict__ bq,
    const float* __restrict__ qg, const float* __restrict__ qb,
    const float* __restrict__ qm, const float* __restrict__ qv,
    const float* __restrict__ Wk, const float* __restrict__ bk,
    const float* __restrict__ kg, const float* __restrict__ kb,
    const float* __restrict__ km, const float* __restrict__ kv,
    const float* __restrict__ Wv, const float* __restrict__ bv,
    const float* __restrict__ vg, const float* __restrict__ vb,
    const float* __restrict__ vm, const float* __restrict__ vv)
{
    int idx = blockIdx.x * blockDim.x + threadIdx.x;
    if (idx >= OTOT * CIN) return;
    int o = idx >> 9;
    int c = idx & 511;
    const float *W, *bb, *g, *be, *mu, *va;
    int ol;
    if (o < 128)      { W = Wq; bb = bq; g = qg; be = qb; mu = qm; va = qv; ol = o; }
    else if (o < 256) { W = Wk; bb = bk; g = kg; be = kb; mu = km; va = kv; ol = o - 128; }
    else              { W = Wv; bb = bv; g = vg; be = vb; mu = vm; va = vv; ol = o - 256; }
    float s = g[ol] * rsqrtf(va[ol] + 1e-5f);
    g_Weff[idx] = W[ol * CIN + c] * s;
    if (c == 0) g_beff[o] = (bb[ol] - mu[ol]) * s + be[ol];
}

// ---------------- kernel 2: pos = rel_h + rel_w, [h][d][n] -----------------
__global__ void pos_kernel(const float* __restrict__ rel_h,
                           const float* __restrict__ rel_w)
{
    int idx = blockIdx.x * blockDim.x + threadIdx.x;  // HEADS*DH*N = 131072
    if (idx >= HEADS_ * DH_ * N_) return;
    int n  = idx & (N_ - 1);
    int hd = idx >> 10;            // h*32 + d
    int w  = n >> 5;
    int hh = n & 31;
    g_pos[idx] = rel_h[hd * 32 + hh] + rel_w[hd * 32 + w];
}

// ---------------- kernel 3: fused QKV GEMM  Y[768,1024] = Weff @ x_b -------
// Tile: BM=64, BN=64, BK=16; 256 threads; rows 4*ty+i, col pairs 2*tx+32p.
__global__ __launch_bounds__(256) void qkv_gemm(const float* __restrict__ x)
{
    __shared__ float As[16][68];   // As[kk][m]  (A transposed in smem)
    __shared__ float Bs[16][68];   // Bs[kk][n]

    int b  = blockIdx.z;
    int m0 = blockIdx.y * 64;
    int n0 = blockIdx.x * 64;
    int tid = threadIdx.x;
    int ty = tid >> 4, tx = tid & 15;
    const float* xb = x + (size_t)b * CIN * N_;

    ull acc[4][2];
#pragma unroll
    for (int i = 0; i < 4; i++) { acc[i][0] = 0ull; acc[i][1] = 0ull; }

    for (int k0 = 0; k0 < CIN; k0 += 16) {
        // load A tile 64x16 (one float4 per thread), transpose into smem
        {
            int row = tid >> 2;            // 0..63
            int cg  = (tid & 3) * 4;       // 0,4,8,12
            float4 av = *(const float4*)(g_Weff + (m0 + row) * CIN + k0 + cg);
            As[cg + 0][row] = av.x;
            As[cg + 1][row] = av.y;
            As[cg + 2][row] = av.z;
            As[cg + 3][row] = av.w;
        }
        // load B tile 16x64 (4 floats per thread, coalesced 64-float runs)
        {
            int nn = tid & 63;
            int kk = tid >> 6;             // 0..3
#pragma unroll
            for (int it = 0; it < 4; it++)
                Bs[kk + it * 4][nn] = xb[(size_t)(k0 + kk + it * 4) * N_ + n0 + nn];
        }
        __syncthreads();
#pragma unroll
        for (int kk = 0; kk < 16; kk++) {
            float4 a4 = *(const float4*)(&As[kk][4 * ty]);
            ull ad0 = f2dup(a4.x), ad1 = f2dup(a4.y), ad2 = f2dup(a4.z), ad3 = f2dup(a4.w);
            ull b0 = lds64(&Bs[kk][2 * tx]);
            ull b1 = lds64(&Bs[kk][2 * tx + 32]);
            acc[0][0] = f2fma(ad0, b0, acc[0][0]);
            acc[0][1] = f2fma(ad0, b1, acc[0][1]);
            acc[1][0] = f2fma(ad1, b0, acc[1][0]);
            acc[1][1] = f2fma(ad1, b1, acc[1][1]);
            acc[2][0] = f2fma(ad2, b0, acc[2][0]);
            acc[2][1] = f2fma(ad2, b1, acc[2][1]);
            acc[3][0] = f2fma(ad3, b0, acc[3][0]);
            acc[3][1] = f2fma(ad3, b1, acc[3][1]);
        }
        __syncthreads();
    }

    // epilogue: scatter into q / k / v layouts with bias (paired STG.64)
#pragma unroll
    for (int i = 0; i < 4; i++) {
        int o = m0 + 4 * ty + i;
        float bias = g_beff[o];
        float* dst;
        if (o < 128)      dst = g_q + (size_t)(b * 128 + o) * N_;
        else if (o < 256) dst = g_k + (size_t)(b * 128 + (o - 128)) * N_;
        else              dst = g_v + (size_t)(b * 512 + (o - 256)) * N_;
#pragma unroll
        for (int p = 0; p < 2; p++) {
            float lo, hi; f2upk(acc[i][p], lo, hi);
            float2 w; w.x = lo + bias; w.y = hi + bias;
            *reinterpret_cast<float2*>(dst + n0 + 2 * tx + 32 * p) = w;
        }
    }
}

// ---------------- kernel 4: fused flash attention + residual ---------------
// Per CTA: one (b, h) and 64 query rows.  d'=64 (q||pos vs k||q), dv=128.
// Smem: Qs[64][66], Ks[64][66], Ps[64][66], Vs[64][130] (Os reuses Vs, pitch 65)
#define QP 66
#define VP 130
#define ATTN_SMEM_FLOATS (3 * 64 * QP + 64 * VP)
#define ATTN_SMEM_BYTES  (ATTN_SMEM_FLOATS * 4)

__global__ __launch_bounds__(256) void attn_kernel(const float* __restrict__ x,
                                                   float* __restrict__ out)
{
    extern __shared__ float sm[];
    float* Qs = sm;                 // Qs[d*QP + r]
    float* Ks = sm + 64 * QP;       // Ks[d*QP + s]
    float* Ps = sm + 2 * 64 * QP;   // Ps[s*QP + r]  (transposed P)
    float* Vs = sm + 3 * 64 * QP;   // Vs[s*VP + c]  (reused as Os[c*65 + r])

    int n0 = blockIdx.x * 64;
    int h  = blockIdx.y;
    int b  = blockIdx.z;
    int tid = threadIdx.x;
    int ty = tid >> 4, tx = tid & 15;

    const float* qbh  = g_q + (size_t)(b * 128 + h * 32) * N_;   // [d][n]
    const float* kbh  = g_k + (size_t)(b * 128 + h * 32) * N_;
    const float* vbh  = g_v + (size_t)(b * 512 + h * 128) * N_;  // [c][n]
    const float* posh = g_pos + (size_t)h * 32 * N_;

    // fill Q' (q rows then pos rows), transposed: Qs[d][r]
    for (int idx = tid; idx < 64 * 64; idx += 256) {
        int r = idx & 63, d = idx >> 6;
        Qs[d * QP + r] = (d < 32) ? qbh[(size_t)d * N_ + n0 + r]
                                  : posh[(size_t)(d - 32) * N_ + n0 + r];
    }

    float m[4], l[4];
    ull O2[4][4];
#pragma unroll
    for (int i = 0; i < 4; i++) {
        m[i] = -1e30f; l[i] = 0.f;
#pragma unroll
        for (int j = 0; j < 4; j++) O2[i][j] = 0ull;
    }
    __syncthreads();

    for (int s0 = 0; s0 < N_; s0 += 64) {
        // fill K' = [k ; q] (transposed) and V (transposed: Vs[s][c], c-pairs)
        for (int idx = tid; idx < 64 * 64; idx += 256) {
            int s = idx & 63, d = idx >> 6;
            Ks[d * QP + s] = (d < 32) ? kbh[(size_t)d * N_ + s0 + s]
                                      : qbh[(size_t)(d - 32) * N_ + s0 + s];
        }
        for (int idx = tid; idx < 64 * 64; idx += 256) {
            int s = idx & 63, cp = idx >> 6;   // cp = column pair 0..63
            float2 w;
            w.x = vbh[(size_t)(2 * cp) * N_ + s0 + s];
            w.y = vbh[(size_t)(2 * cp + 1) * N_ + s0 + s];
            *reinterpret_cast<float2*>(Vs + s * VP + 2 * cp) = w;
        }
        __syncthreads();

        // GEMM1: S[64r x 64s] over d'=64; rows 4ty+i, col pairs 2tx+32p
        ull S2[4][2];
#pragma unroll
        for (int i = 0; i < 4; i++) { S2[i][0] = 0ull; S2[i][1] = 0ull; }

#pragma unroll 4
        for (int d = 0; d < 64; d++) {
            ull a01 = lds64(Qs + d * QP + 4 * ty);
            ull a23 = lds64(Qs + d * QP + 4 * ty + 2);
            float a0, a1, a2, a3;
            f2upk(a01, a0, a1); f2upk(a23, a2, a3);
            ull ad0 = f2dup(a0), ad1 = f2dup(a1), ad2 = f2dup(a2), ad3 = f2dup(a3);
            ull k0 = lds64(Ks + d * QP + 2 * tx);
            ull k1 = lds64(Ks + d * QP + 2 * tx + 32);
            S2[0][0] = f2fma(ad0, k0, S2[0][0]);
            S2[0][1] = f2fma(ad0, k1, S2[0][1]);
            S2[1][0] = f2fma(ad1, k0, S2[1][0]);
            S2[1][1] = f2fma(ad1, k1, S2[1][1]);
            S2[2][0] = f2fma(ad2, k0, S2[2][0]);
            S2[2][1] = f2fma(ad2, k1, S2[2][1]);
            S2[3][0] = f2fma(ad3, k0, S2[3][0]);
            S2[3][1] = f2fma(ad3, k1, S2[3][1]);
        }

        // online softmax (each row's 64 cols live entirely in the 16 tx lanes)
#pragma unroll
        for (int i = 0; i < 4; i++) {
            float s0v, s1v, s2v, s3v;
            f2upk(S2[i][0], s0v, s1v);
            f2upk(S2[i][1], s2v, s3v);
            float rm = fmaxf(fmaxf(s0v, s1v), fmaxf(s2v, s3v));
#pragma unroll
            for (int off = 8; off >= 1; off >>= 1)
                rm = fmaxf(rm, __shfl_xor_sync(0xffffffffu, rm, off));
            float mn = fmaxf(m[i], rm);
            float corr = __expf(m[i] - mn);
            m[i] = mn;
            float p0 = __expf(s0v - mn), p1 = __expf(s1v - mn);
            float p2 = __expf(s2v - mn), p3 = __expf(s3v - mn);
            float rs = (p0 + p1) + (p2 + p3);
#pragma unroll
            for (int off = 8; off >= 1; off >>= 1)
                rs += __shfl_xor_sync(0xffffffffu, rs, off);
            l[i] = l[i] * corr + rs;
            ull cd = f2dup(corr);
#pragma unroll
            for (int j = 0; j < 4; j++) O2[i][j] = f2mul(O2[i][j], cd);
            int r = 4 * ty + i;
            Ps[(2 * tx)      * QP + r] = p0;
            Ps[(2 * tx + 1)  * QP + r] = p1;
            Ps[(2 * tx + 32) * QP + r] = p2;
            Ps[(2 * tx + 33) * QP + r] = p3;
        }
        __syncthreads();

        // GEMM2: O[64r x 128c] += P[64r x 64s] @ V[64s x 128c]; col pairs 2tx+32j
#pragma unroll 2
        for (int s = 0; s < 64; s++) {
            ull p01 = lds64(Ps + s * QP + 4 * ty);
            ull p23 = lds64(Ps + s * QP + 4 * ty + 2);
            float p0, p1, p2, p3;
            f2upk(p01, p0, p1); f2upk(p23, p2, p3);
            ull pd0 = f2dup(p0), pd1 = f2dup(p1), pd2 = f2dup(p2), pd3 = f2dup(p3);
            ull v0 = lds64(Vs + s * VP + 2 * tx);
            ull v1 = lds64(Vs + s * VP + 2 * tx + 32);
            ull v2 = lds64(Vs + s * VP + 2 * tx + 64);
            ull v3 = lds64(Vs + s * VP + 2 * tx + 96);
            O2[0][0] = f2fma(pd0, v0, O2[0][0]);
            O2[0][1] = f2fma(pd0, v1, O2[0][1]);
            O2[0][2] = f2fma(pd0, v2, O2[0][2]);
            O2[0][3] = f2fma(pd0, v3, O2[0][3]);
            O2[1][0] = f2fma(pd1, v0, O2[1][0]);
            O2[1][1] = f2fma(pd1, v1, O2[1][1]);
            O2[1][2] = f2fma(pd1, v2, O2[1][2]);
            O2[1][3] = f2fma(pd1, v3, O2[1][3]);
            O2[2][0] = f2fma(pd2, v0, O2[2][0]);
            O2[2][1] = f2fma(pd2, v1, O2[2][1]);
            O2[2][2] = f2fma(pd2, v2, O2[2][2]);
            O2[2][3] = f2fma(pd2, v3, O2[2][3]);
            O2[3][0] = f2fma(pd3, v0, O2[3][0]);
            O2[3][1] = f2fma(pd3, v1, O2[3][1]);
            O2[3][2] = f2fma(pd3, v2, O2[3][2]);
            O2[3][3] = f2fma(pd3, v3, O2[3][3]);
        }
        __syncthreads();   // protects Ks/Vs/Ps reuse next iteration
    }

    // normalize + transpose through smem for coalesced global writes
    float* Os = Vs;   // Os[c*65 + r]: 128*65 = 8320 floats = Vs region exactly
#pragma unroll
    for (int i = 0; i < 4; i++) {
        float inv = 1.f / l[i];
        int r = 4 * ty + i;
#pragma unroll
        for (int j = 0; j < 4; j++) {
            float lo, hi; f2upk(O2[i][j], lo, hi);
            int c = 2 * tx + 32 * j;
            Os[c * 65 + r]       = lo * inv;
            Os[(c + 1) * 65 + r] = hi * inv;
        }
    }
    __syncthreads();

    const float* xb = x   + (size_t)(b * 512 + h * 128) * N_;
    float*       ob = out + (size_t)(b * 512 + h * 128) * N_;
    for (int idx = tid; idx < 128 * 64; idx += 256) {
        int r = idx & 63, c = idx >> 6;
        ob[(size_t)c * N_ + n0 + r] = Os[c * 65 + r] + xb[(size_t)c * N_ + n0 + r];
    }
}

// ---------------- launcher -------------------------------------------------
extern "C" void kernel_launch(void* const* d_in, const int* in_sizes, int n_in,
                              void* d_out, int out_size)
{
    const float* x = (const float*)d_in[0];

    fold_kernel<<<(OTOT * CIN + 255) / 256, 256>>>(
        (const float*)d_in[1],  (const float*)d_in[2],
        (const float*)d_in[3],  (const float*)d_in[4],
        (const float*)d_in[5],  (const float*)d_in[6],
        (const float*)d_in[7],  (const float*)d_in[8],
        (const float*)d_in[9],  (const float*)d_in[10],
        (const float*)d_in[11], (const float*)d_in[12],
        (const float*)d_in[13], (const float*)d_in[14],
        (const float*)d_in[15], (const float*)d_in[16],
        (const float*)d_in[17], (const float*)d_in[18]);

    pos_kernel<<<(HEADS_ * DH_ * N_ + 255) / 256, 256>>>(
        (const float*)d_in[19], (const float*)d_in[20]);

    qkv_gemm<<<dim3(N_ / 64, OTOT / 64, B_), 256>>>(x);

    cudaFuncSetAttribute(attn_kernel,
                         cudaFuncAttributeMaxDynamicSharedMemorySize,
                         ATTN_SMEM_BYTES);
    attn_kernel<<<dim3(N_ / 64, HEADS_, B_), 256, ATTN_SMEM_BYTES>>>(x, (float*)d_out);
}

// round 8
// speedup vs baseline: 1.2473x; 1.0767x over previous
#include <cuda_runtime.h>

// Problem constants
#define B_    16
#define CIN   512
#define N_    1024
#define HEADS_ 4
#define DH_   32
#define DV_   128
#define OTOT  768     // 128 (q) + 128 (k) + 512 (v) output channels

typedef unsigned long long ull;

// ---------------- f32x2 packed helpers (sm_103a FFMA2 path) ----------------
__device__ __forceinline__ ull f2pk(float lo, float hi) {
    ull r; asm("mov.b64 %0, {%1, %2};" : "=l"(r) : "f"(lo), "f"(hi)); return r;
}
__device__ __forceinline__ ull f2dup(float x) {
    ull r; asm("mov.b64 %0, {%1, %1};" : "=l"(r) : "f"(x)); return r;
}
__device__ __forceinline__ void f2upk(ull v, float& lo, float& hi) {
    asm("mov.b64 {%0, %1}, %2;" : "=f"(lo), "=f"(hi) : "l"(v));
}
__device__ __forceinline__ ull f2fma(ull a, ull b, ull c) {
    ull d; asm("fma.rn.f32x2 %0, %1, %2, %3;" : "=l"(d) : "l"(a), "l"(b), "l"(c)); return d;
}
__device__ __forceinline__ ull f2mul(ull a, ull b) {
    ull d; asm("mul.rn.f32x2 %0, %1, %2;" : "=l"(d) : "l"(a), "l"(b)); return d;
}
__device__ __forceinline__ ull lds64(const float* p) {
    float2 v = *reinterpret_cast<const float2*>(p);
    return f2pk(v.x, v.y);
}

// ---------------- scratch (device globals; no allocation allowed) ----------
__device__ float g_Weff[OTOT * CIN];       // folded conv+BN weights
__device__ float g_beff[OTOT];             // folded bias
__device__ float g_q[B_ * 128 * N_];       // [b][h*32+d][n]
__device__ float g_k[B_ * 128 * N_];       // [b][h*32+d][n]
__device__ float g_v[B_ * 512 * N_];       // [b][h*128+c][n]
__device__ float g_pos[HEADS_ * DH_ * N_]; // [h][d][n]

// ---------------- kernel 1: fold BN into conv weights ----------------------
__global__ void fold_kernel(
    const float* __restrict__ Wq, const float* __restrict__ bq,
    const float* __restrict__ qg, const float* __restrict__ qb,
    const float* __restrict__ qm, const float* __restrict__ qv,
    const float* __restrict__ Wk, const float* __restrict__ bk,
    const float* __restrict__ kg, const float* __restrict__ kb,
    const float* __restrict__ km, const float* __restrict__ kv,
    const float* __restrict__ Wv, const float* __restrict__ bv,
    const float* __restrict__ vg, const float* __restrict__ vb,
    const float* __restrict__ vm, const float* __restrict__ vv)
{
    int idx = blockIdx.x * blockDim.x + threadIdx.x;
    if (idx >= OTOT * CIN) return;
    int o = idx >> 9;
    int c = idx & 511;
    const float *W, *bb, *g, *be, *mu, *va;
    int ol;
    if (o < 128)      { W = Wq; bb = bq; g = qg; be = qb; mu = qm; va = qv; ol = o; }
    else if (o < 256) { W = Wk; bb = bk; g = kg; be = kb; mu = km; va = kv; ol = o - 128; }
    else              { W = Wv; bb = bv; g = vg; be = vb; mu = vm; va = vv; ol = o - 256; }
    float s = g[ol] * rsqrtf(va[ol] + 1e-5f);
    g_Weff[idx] = W[ol * CIN + c] * s;
    if (c == 0) g_beff[o] = (bb[ol] - mu[ol]) * s + be[ol];
}

// ---------------- kernel 2: pos = rel_h + rel_w, [h][d][n] -----------------
__global__ void pos_kernel(const float* __restrict__ rel_h,
                           const float* __restrict__ rel_w)
{
    int idx = blockIdx.x * blockDim.x + threadIdx.x;  // HEADS*DH*N = 131072
    if (idx >= HEADS_ * DH_ * N_) return;
    int n  = idx & (N_ - 1);
    int hd = idx >> 10;            // h*32 + d
    int w  = n >> 5;
    int hh = n & 31;
    g_pos[idx] = rel_h[hd * 32 + hh] + rel_w[hd * 32 + w];
}

// ---------------- kernel 3: fused QKV GEMM  Y[768,1024] = Weff @ x_b -------
// Tile: BM=64, BN=64, BK=16; 256 threads; rows 4*ty+i, col pairs 2*tx+32p.
__global__ __launch_bounds__(256) void qkv_gemm(const float* __restrict__ x)
{
    __shared__ float As[16][68];   // As[kk][m]  (A transposed in smem)
    __shared__ float Bs[16][68];   // Bs[kk][n]

    int b  = blockIdx.z;
    int m0 = blockIdx.y * 64;
    int n0 = blockIdx.x * 64;
    int tid = threadIdx.x;
    int ty = tid >> 4, tx = tid & 15;
    const float* xb = x + (size_t)b * CIN * N_;

    ull acc[4][2];
#pragma unroll
    for (int i = 0; i < 4; i++) { acc[i][0] = 0ull; acc[i][1] = 0ull; }

    for (int k0 = 0; k0 < CIN; k0 += 16) {
        // load A tile 64x16 (one float4 per thread), transpose into smem
        {
            int row = tid >> 2;            // 0..63
            int cg  = (tid & 3) * 4;       // 0,4,8,12
            float4 av = *(const float4*)(g_Weff + (m0 + row) * CIN + k0 + cg);
            As[cg + 0][row] = av.x;
            As[cg + 1][row] = av.y;
            As[cg + 2][row] = av.z;
            As[cg + 3][row] = av.w;
        }
        // load B tile 16x64 (4 floats per thread, coalesced 64-float runs)
        {
            int nn = tid & 63;
            int kk = tid >> 6;             // 0..3
#pragma unroll
            for (int it = 0; it < 4; it++)
                Bs[kk + it * 4][nn] = xb[(size_t)(k0 + kk + it * 4) * N_ + n0 + nn];
        }
        __syncthreads();
#pragma unroll
        for (int kk = 0; kk < 16; kk++) {
            float4 a4 = *(const float4*)(&As[kk][4 * ty]);
            ull ad0 = f2dup(a4.x), ad1 = f2dup(a4.y), ad2 = f2dup(a4.z), ad3 = f2dup(a4.w);
            ull b0 = lds64(&Bs[kk][2 * tx]);
            ull b1 = lds64(&Bs[kk][2 * tx + 32]);
            acc[0][0] = f2fma(ad0, b0, acc[0][0]);
            acc[0][1] = f2fma(ad0, b1, acc[0][1]);
            acc[1][0] = f2fma(ad1, b0, acc[1][0]);
            acc[1][1] = f2fma(ad1, b1, acc[1][1]);
            acc[2][0] = f2fma(ad2, b0, acc[2][0]);
            acc[2][1] = f2fma(ad2, b1, acc[2][1]);
            acc[3][0] = f2fma(ad3, b0, acc[3][0]);
            acc[3][1] = f2fma(ad3, b1, acc[3][1]);
        }
        __syncthreads();
    }

    // epilogue: scatter into q / k / v layouts with bias (paired STG.64)
#pragma unroll
    for (int i = 0; i < 4; i++) {
        int o = m0 + 4 * ty + i;
        float bias = g_beff[o];
        float* dst;
        if (o < 128)      dst = g_q + (size_t)(b * 128 + o) * N_;
        else if (o < 256) dst = g_k + (size_t)(b * 128 + (o - 128)) * N_;
        else              dst = g_v + (size_t)(b * 512 + (o - 256)) * N_;
#pragma unroll
        for (int p = 0; p < 2; p++) {
            float lo, hi; f2upk(acc[i][p], lo, hi);
            float2 w; w.x = lo + bias; w.y = hi + bias;
            *reinterpret_cast<float2*>(dst + n0 + 2 * tx + 32 * p) = w;
        }
    }
}

// ---------------- kernel 4: fused flash attention + residual ---------------
// Per CTA: one (b, h) and 64 query rows.  d'=64 (q||pos vs k||q), dv=128.
// Smem: Qs[64][66], Ks[64][66], Vs[64][130].  P stays in registers; GEMM2
// fetches p[s][row] via __shfl from the lane that owns column s (same ty-half).
// 65.5 KB smem -> 3 CTAs/SM.
#define QP 66
#define VP 130
#define ATTN_SMEM_FLOATS (2 * 64 * QP + 64 * VP)
#define ATTN_SMEM_BYTES  (ATTN_SMEM_FLOATS * 4)

__global__ __launch_bounds__(256, 3) void attn_kernel(const float* __restrict__ x,
                                                      float* __restrict__ out)
{
    extern __shared__ float sm[];
    float* Qs = sm;                 // Qs[d*QP + r]
    float* Ks = sm + 64 * QP;       // Ks[d*QP + s]
    float* Vs = sm + 2 * 64 * QP;   // Vs[s*VP + c]

    int n0 = blockIdx.x * 64;
    int h  = blockIdx.y;
    int b  = blockIdx.z;
    int tid = threadIdx.x;
    int ty = tid >> 4, tx = tid & 15;
    int halfbase = tid & 16;        // lane-half base within the warp (same ty group)

    const float* qbh  = g_q + (size_t)(b * 128 + h * 32) * N_;   // [d][n]
    const float* kbh  = g_k + (size_t)(b * 128 + h * 32) * N_;
    const float* vbh  = g_v + (size_t)(b * 512 + h * 128) * N_;  // [c][n]
    const float* posh = g_pos + (size_t)h * 32 * N_;

    // fill Q' (q rows then pos rows), transposed: Qs[d][r]
    for (int idx = tid; idx < 64 * 64; idx += 256) {
        int r = idx & 63, d = idx >> 6;
        Qs[d * QP + r] = (d < 32) ? qbh[(size_t)d * N_ + n0 + r]
                                  : posh[(size_t)(d - 32) * N_ + n0 + r];
    }

    float m[4], l[4];
    ull O2[4][4];
#pragma unroll
    for (int i = 0; i < 4; i++) {
        m[i] = -1e30f; l[i] = 0.f;
#pragma unroll
        for (int j = 0; j < 4; j++) O2[i][j] = 0ull;
    }
    __syncthreads();

    for (int s0 = 0; s0 < N_; s0 += 64) {
        // fill K' = [k ; q] (transposed) and V (transposed: Vs[s][c], c-pairs)
        for (int idx = tid; idx < 64 * 64; idx += 256) {
            int s = idx & 63, d = idx >> 6;
            Ks[d * QP + s] = (d < 32) ? kbh[(size_t)d * N_ + s0 + s]
                                      : qbh[(size_t)(d - 32) * N_ + s0 + s];
        }
        for (int idx = tid; idx < 64 * 64; idx += 256) {
            int s = idx & 63, cp = idx >> 6;   // cp = column pair 0..63
            float2 w;
            w.x = vbh[(size_t)(2 * cp) * N_ + s0 + s];
            w.y = vbh[(size_t)(2 * cp + 1) * N_ + s0 + s];
            *reinterpret_cast<float2*>(Vs + s * VP + 2 * cp) = w;
        }
        __syncthreads();

        // GEMM1: S[64r x 64s] over d'=64; rows 4ty+i, col pairs 2tx+32p
        ull S2[4][2];
#pragma unroll
        for (int i = 0; i < 4; i++) { S2[i][0] = 0ull; S2[i][1] = 0ull; }

#pragma unroll 4
        for (int d = 0; d < 64; d++) {
            ull a01 = lds64(Qs + d * QP + 4 * ty);
            ull a23 = lds64(Qs + d * QP + 4 * ty + 2);
            float a0, a1, a2, a3;
            f2upk(a01, a0, a1); f2upk(a23, a2, a3);
            ull ad0 = f2dup(a0), ad1 = f2dup(a1), ad2 = f2dup(a2), ad3 = f2dup(a3);
            ull k0 = lds64(Ks + d * QP + 2 * tx);
            ull k1 = lds64(Ks + d * QP + 2 * tx + 32);
            S2[0][0] = f2fma(ad0, k0, S2[0][0]);
            S2[0][1] = f2fma(ad0, k1, S2[0][1]);
            S2[1][0] = f2fma(ad1, k0, S2[1][0]);
            S2[1][1] = f2fma(ad1, k1, S2[1][1]);
            S2[2][0] = f2fma(ad2, k0, S2[2][0]);
            S2[2][1] = f2fma(ad2, k1, S2[2][1]);
            S2[3][0] = f2fma(ad3, k0, S2[3][0]);
            S2[3][1] = f2fma(ad3, k1, S2[3][1]);
        }

        // online softmax; p kept in registers: P4[i][j] = p for row 4ty+i,
        // col {2tx, 2tx+1, 2tx+32, 2tx+33}[j]
        float P4[4][4];
#pragma unroll
        for (int i = 0; i < 4; i++) {
            float s0v, s1v, s2v, s3v;
            f2upk(S2[i][0], s0v, s1v);
            f2upk(S2[i][1], s2v, s3v);
            float rm = fmaxf(fmaxf(s0v, s1v), fmaxf(s2v, s3v));
#pragma unroll
            for (int off = 8; off >= 1; off >>= 1)
                rm = fmaxf(rm, __shfl_xor_sync(0xffffffffu, rm, off));
            float mn = fmaxf(m[i], rm);
            float corr = __expf(m[i] - mn);
            m[i] = mn;
            float p0 = __expf(s0v - mn), p1 = __expf(s1v - mn);
            float p2 = __expf(s2v - mn), p3 = __expf(s3v - mn);
            float rs = (p0 + p1) + (p2 + p3);
#pragma unroll
            for (int off = 8; off >= 1; off >>= 1)
                rs += __shfl_xor_sync(0xffffffffu, rs, off);
            l[i] = l[i] * corr + rs;
            ull cd = f2dup(corr);
#pragma unroll
            for (int j = 0; j < 4; j++) O2[i][j] = f2mul(O2[i][j], cd);
            P4[i][0] = p0; P4[i][1] = p1; P4[i][2] = p2; P4[i][3] = p3;
        }
        // no CTA sync needed here: GEMM2 consumes P via intra-warp shuffles

        // GEMM2: O[64r x 128c] += P[64r x 64s] @ V[64s x 128c]; col pairs 2tx+32j
        // p[s][4ty+i] comes from lane (halfbase | (s&31)>>1), register (s&1)+2*(s>>5)
#pragma unroll
        for (int sh = 0; sh < 2; sh++) {
#pragma unroll 4
            for (int s2 = 0; s2 < 32; s2++) {
                int s = sh * 32 + s2;
                int src = halfbase | (s2 >> 1);
                ull pd0, pd1, pd2, pd3;
                if ((s2 & 1) == 0) {
                    pd0 = f2dup(__shfl_sync(0xffffffffu, P4[0][2 * sh], src));
                    pd1 = f2dup(__shfl_sync(0xffffffffu, P4[1][2 * sh], src));
                    pd2 = f2dup(__shfl_sync(0xffffffffu, P4[2][2 * sh], src));
                    pd3 = f2dup(__shfl_sync(0xffffffffu, P4[3][2 * sh], src));
                } else {
                    pd0 = f2dup(__shfl_sync(0xffffffffu, P4[0][2 * sh + 1], src));
                    pd1 = f2dup(__shfl_sync(0xffffffffu, P4[1][2 * sh + 1], src));
                    pd2 = f2dup(__shfl_sync(0xffffffffu, P4[2][2 * sh + 1], src));
                    pd3 = f2dup(__shfl_sync(0xffffffffu, P4[3][2 * sh + 1], src));
                }
                ull v0 = lds64(Vs + s * VP + 2 * tx);
                ull v1 = lds64(Vs + s * VP + 2 * tx + 32);
                ull v2 = lds64(Vs + s * VP + 2 * tx + 64);
                ull v3 = lds64(Vs + s * VP + 2 * tx + 96);
                O2[0][0] = f2fma(pd0, v0, O2[0][0]);
                O2[0][1] = f2fma(pd0, v1, O2[0][1]);
                O2[0][2] = f2fma(pd0, v2, O2[0][2]);
                O2[0][3] = f2fma(pd0, v3, O2[0][3]);
                O2[1][0] = f2fma(pd1, v0, O2[1][0]);
                O2[1][1] = f2fma(pd1, v1, O2[1][1]);
                O2[1][2] = f2fma(pd1, v2, O2[1][2]);
                O2[1][3] = f2fma(pd1, v3, O2[1][3]);
                O2[2][0] = f2fma(pd2, v0, O2[2][0]);
                O2[2][1] = f2fma(pd2, v1, O2[2][1]);
                O2[2][2] = f2fma(pd2, v2, O2[2][2]);
                O2[2][3] = f2fma(pd2, v3, O2[2][3]);
                O2[3][0] = f2fma(pd3, v0, O2[3][0]);
                O2[3][1] = f2fma(pd3, v1, O2[3][1]);
                O2[3][2] = f2fma(pd3, v2, O2[3][2]);
                O2[3][3] = f2fma(pd3, v3, O2[3][3]);
            }
        }
        __syncthreads();   // protects Ks/Vs reuse next iteration
    }

    // normalize + transpose through smem for coalesced global writes
    float* Os = sm;   // Os[c*65 + r]: 128*65 = 8320 floats, reuses Qs+Ks region
#pragma unroll
    for (int i = 0; i < 4; i++) {
        float inv = 1.f / l[i];
        int r = 4 * ty + i;
#pragma unroll
        for (int j = 0; j < 4; j++) {
            float lo, hi; f2upk(O2[i][j], lo, hi);
            int c = 2 * tx + 32 * j;
            Os[c * 65 + r]       = lo * inv;
            Os[(c + 1) * 65 + r] = hi * inv;
        }
    }
    __syncthreads();

    const float* xb = x   + (size_t)(b * 512 + h * 128) * N_;
    float*       ob = out + (size_t)(b * 512 + h * 128) * N_;
    for (int idx = tid; idx < 128 * 64; idx += 256) {
        int r = idx & 63, c = idx >> 6;
        ob[(size_t)c * N_ + n0 + r] = Os[c * 65 + r] + xb[(size_t)c * N_ + n0 + r];
    }
}

// ---------------- launcher -------------------------------------------------
extern "C" void kernel_launch(void* const* d_in, const int* in_sizes, int n_in,
                              void* d_out, int out_size)
{
    const float* x = (const float*)d_in[0];

    fold_kernel<<<(OTOT * CIN + 255) / 256, 256>>>(
        (const float*)d_in[1],  (const float*)d_in[2],
        (const float*)d_in[3],  (const float*)d_in[4],
        (const float*)d_in[5],  (const float*)d_in[6],
        (const float*)d_in[7],  (const float*)d_in[8],
        (const float*)d_in[9],  (const float*)d_in[10],
        (const float*)d_in[11], (const float*)d_in[12],
        (const float*)d_in[13], (const float*)d_in[14],
        (const float*)d_in[15], (const float*)d_in[16],
        (const float*)d_in[17], (const float*)d_in[18]);

    pos_kernel<<<(HEADS_ * DH_ * N_ + 255) / 256, 256>>>(
        (const float*)d_in[19], (const float*)d_in[20]);

    qkv_gemm<<<dim3(N_ / 64, OTOT / 64, B_), 256>>>(x);

    cudaFuncSetAttribute(attn_kernel,
                         cudaFuncAttributeMaxDynamicSharedMemorySize,
                         ATTN_SMEM_BYTES);
    attn_kernel<<<dim3(N_ / 64, HEADS_, B_), 256, ATTN_SMEM_BYTES>>>(x, (float*)d_out);
}